// round 2
// baseline (speedup 1.0000x reference)
#include <cuda_runtime.h>

#define B_ 2
#define T_ 192
#define C_ 512
#define H_ 8
#define D_ 64
#define PROJC (5 * C_)  // 2560

// scratch (device globals; no allocation allowed)
__device__ float g_proj[B_ * T_ * PROJC];   // (B*T, 2560)
__device__ float g_attn[B_ * T_ * C_];      // (B*T, 512)  attention output, heads merged

// ---------------------------------------------------------------------------
// Generic tiled GEMM + bias: C[M,N] = A[M,K] @ Bm[K,N] + bias[N]
// 64x64 tile, 256 threads, 4x4 register microtile, K-tile 16.
// M,N divisible by 64; K divisible by 16 (holds for both uses).
// ---------------------------------------------------------------------------
__global__ __launch_bounds__(256) void gemm_bias_kernel(
    const float* __restrict__ A, const float* __restrict__ Bm,
    const float* __restrict__ bias, float* __restrict__ C,
    int M, int N, int K)
{
    __shared__ float AsT[16][65];   // transposed A tile, padded
    __shared__ float Bs[16][64];

    const int t  = threadIdx.x;
    const int tx = t & 15;
    const int ty = t >> 4;
    const int row0 = blockIdx.y * 64;
    const int col0 = blockIdx.x * 64;

    float acc[4][4] = {};

    for (int kt = 0; kt < K; kt += 16) {
        // load A tile 64x16 (coalesced float4), store transposed
        {
            int r  = t >> 2;          // 0..63
            int c4 = (t & 3) << 2;    // 0,4,8,12
            float4 av = *(const float4*)&A[(size_t)(row0 + r) * K + kt + c4];
            AsT[c4 + 0][r] = av.x;
            AsT[c4 + 1][r] = av.y;
            AsT[c4 + 2][r] = av.z;
            AsT[c4 + 3][r] = av.w;
        }
        // load B tile 16x64 (coalesced float4)
        {
            int r  = t >> 4;          // 0..15
            int c4 = (t & 15) << 2;
            *(float4*)&Bs[r][c4] = *(const float4*)&Bm[(size_t)(kt + r) * N + col0 + c4];
        }
        __syncthreads();

        #pragma unroll
        for (int kk = 0; kk < 16; kk++) {
            float a[4];
            #pragma unroll
            for (int r = 0; r < 4; r++) a[r] = AsT[kk][(ty << 2) + r];
            float4 bv = *(float4*)&Bs[kk][tx << 2];
            float bb[4] = {bv.x, bv.y, bv.z, bv.w};
            #pragma unroll
            for (int r = 0; r < 4; r++)
                #pragma unroll
                for (int c = 0; c < 4; c++)
                    acc[r][c] += a[r] * bb[c];
        }
        __syncthreads();
    }

    #pragma unroll
    for (int r = 0; r < 4; r++) {
        float4 o;
        int col = col0 + (tx << 2);
        o.x = acc[r][0] + bias[col + 0];
        o.y = acc[r][1] + bias[col + 1];
        o.z = acc[r][2] + bias[col + 2];
        o.w = acc[r][3] + bias[col + 3];
        *(float4*)&C[(size_t)(row0 + (ty << 2) + r) * N + col] = o;
    }
}

// ---------------------------------------------------------------------------
// Fused two-simplicial attention.
// One block per (b, h, i-tile of 8). 256 threads (8 warps; warp w owns i=w).
// Per j-tile of 8 (24 phases):
//   PT[d][m]   = q_i[d]*k1_j[d]          (m = i*8+jj, 64x64)
//   S[m][k]    = sum_d PT[d][m]*K2T[d][k]       GEMM 64x192x64
//   online softmax per i (warp-local), E written transposed ET[k][m]
//   U[m][d]    = sum_k ET[k][m]*V2[k][d]        GEMM 64x64x192
//   acc[i][d]  = acc*alpha_i + sum_jj v1_jj[d]*U[(i,jj)][d]
// Final: out[i][d] = acc[i][d] / Z_i
// ---------------------------------------------------------------------------

// shared memory layout (floats)
#define OFF_Q    0        // 512   Qs[8][64] (prescaled by D^-0.5)
#define OFF_K1   512      // 512   K1s[8][64]
#define OFF_V1   1024     // 512   V1s[8][64]
#define OFF_ACC  1536     // 512   acc[8][64]
#define OFF_K2T  2048     // 12288 K2T[64][192]
#define OFF_V2   14336    // 12288 V2s[192][64]
#define OFF_PT   26624    // 4096  PT[64][64]
#define OFF_ET   30720    // 13056 ET[192][68]  (also staging [192][65] at init)
#define OFF_M    43776    // 8
#define OFF_Z    43784    // 8
#define OFF_AL   43792    // 8
#define SMEM_FLOATS 43800

__global__ __launch_bounds__(256, 1) void attn_kernel(
    const float* __restrict__ proj, float* __restrict__ outp)
{
    extern __shared__ float sm[];
    float* Qs   = sm + OFF_Q;
    float* K1s  = sm + OFF_K1;
    float* V1s  = sm + OFF_V1;
    float* accS = sm + OFF_ACC;
    float* K2T  = sm + OFF_K2T;
    float* V2s  = sm + OFF_V2;
    float* PT   = sm + OFF_PT;
    float* ET   = sm + OFF_ET;
    float* sM   = sm + OFF_M;
    float* sZ   = sm + OFF_Z;
    float* sAl  = sm + OFF_AL;

    const int t    = threadIdx.x;
    const int tx   = t & 15;
    const int ty   = t >> 4;
    const int warp = t >> 5;      // == i within tile
    const int lane = t & 31;
    const int b    = blockIdx.z;
    const int h    = blockIdx.y;
    const int i0   = blockIdx.x * 8;

    const float* base = proj + (size_t)b * T_ * PROJC + h * D_;
    // column offsets within a proj row: q:0, k1:C_, v1:2C_, k2:3C_, v2:4C_

    // ---- init: Q (scaled), acc, M/Z, V2, stage K2 ----
    for (int idx = t; idx < 512; idx += 256) {
        int r = idx >> 6, d = idx & 63;
        Qs[idx]   = base[(size_t)(i0 + r) * PROJC + d] * 0.125f;  // D^-0.5
        accS[idx] = 0.f;
    }
    if (t < 8) { sM[t] = -3.0e38f; sZ[t] = 0.f; sAl[t] = 0.f; }
    for (int idx = t; idx < T_ * D_; idx += 256) {
        int k = idx >> 6, d = idx & 63;
        V2s[idx]        = base[(size_t)k * PROJC + 4 * C_ + d];
        ET[k * 65 + d]  = base[(size_t)k * PROJC + 3 * C_ + d];  // staging for K2
    }
    __syncthreads();
    // transpose K2 staging -> K2T[d][k] (conflict-free both directions)
    for (int idx = t; idx < T_ * D_; idx += 256) {
        int d = idx / T_, k = idx - d * T_;
        K2T[d * T_ + k] = ET[k * 65 + d];
    }
    __syncthreads();

    for (int jt = 0; jt < T_; jt += 8) {
        // ---- load K1/V1 rows for this j-tile (float4, coalesced) ----
        {
            int tt = t & 127;
            int jj = tt >> 4, d4 = (tt & 15) << 2;
            const float* src = base + (size_t)(jt + jj) * PROJC +
                               (t < 128 ? C_ : 2 * C_) + d4;
            float* dst = (t < 128 ? K1s : V1s) + jj * 64 + d4;
            *(float4*)dst = *(const float4*)src;
        }
        __syncthreads();

        // ---- PT[d][m] = Qs[i][d] * K1s[jj][d] ----
        #pragma unroll
        for (int l = 0; l < 16; l++) {
            int idx = t + l * 256;        // idx = d*64 + m
            int d = idx >> 6, m = idx & 63;
            PT[idx] = Qs[((m >> 3) << 6) + d] * K1s[((m & 7) << 6) + d];
        }
        __syncthreads();

        // ---- GEMM1: S[m][k], m = ty*4+r, k = p*64 + tx*4 + c ----
        float s[3][4][4] = {};
        #pragma unroll 4
        for (int d = 0; d < 64; d++) {
            float4 af = *(float4*)&PT[(d << 6) + (ty << 2)];
            float a[4] = {af.x, af.y, af.z, af.w};
            #pragma unroll
            for (int p = 0; p < 3; p++) {
                float4 bf = *(float4*)&K2T[d * T_ + p * 64 + (tx << 2)];
                float bb[4] = {bf.x, bf.y, bf.z, bf.w};
                #pragma unroll
                for (int r = 0; r < 4; r++)
                    #pragma unroll
                    for (int c = 0; c < 4; c++)
                        s[p][r][c] += a[r] * bb[c];
            }
        }

        // ---- online softmax (warp-local: warp w holds all of i=w) ----
        float mloc = -3.0e38f;
        #pragma unroll
        for (int p = 0; p < 3; p++)
            #pragma unroll
            for (int r = 0; r < 4; r++)
                #pragma unroll
                for (int c = 0; c < 4; c++)
                    mloc = fmaxf(mloc, s[p][r][c]);
        #pragma unroll
        for (int off = 16; off > 0; off >>= 1)
            mloc = fmaxf(mloc, __shfl_xor_sync(0xffffffffu, mloc, off));

        float Mold  = sM[warp];
        float Mnew  = fmaxf(Mold, mloc);
        float alpha = __expf(Mold - Mnew);
        float lsum  = 0.f;
        #pragma unroll
        for (int p = 0; p < 3; p++)
            #pragma unroll
            for (int c = 0; c < 4; c++) {
                float4 ev;
                ev.x = __expf(s[p][0][c] - Mnew);
                ev.y = __expf(s[p][1][c] - Mnew);
                ev.z = __expf(s[p][2][c] - Mnew);
                ev.w = __expf(s[p][3][c] - Mnew);
                lsum += (ev.x + ev.y) + (ev.z + ev.w);
                int k = p * 64 + (tx << 2) + c;
                *(float4*)&ET[k * 68 + (ty << 2)] = ev;   // E transposed
            }
        #pragma unroll
        for (int off = 16; off > 0; off >>= 1)
            lsum += __shfl_xor_sync(0xffffffffu, lsum, off);
        if (lane == 0) {
            sZ[warp]  = sZ[warp] * alpha + lsum;
            sM[warp]  = Mnew;
            sAl[warp] = alpha;
        }
        __syncthreads();

        // ---- GEMM2: U[m][d] = sum_k ET[k][m]*V2s[k][d] ----
        float u[4][4] = {};
        #pragma unroll 4
        for (int k = 0; k < T_; k++) {
            float4 af = *(float4*)&ET[k * 68 + (ty << 2)];
            float4 bf = *(float4*)&V2s[(k << 6) + (tx << 2)];
            float a[4]  = {af.x, af.y, af.z, af.w};
            float bb[4] = {bf.x, bf.y, bf.z, bf.w};
            #pragma unroll
            for (int r = 0; r < 4; r++)
                #pragma unroll
                for (int c = 0; c < 4; c++)
                    u[r][c] += a[r] * bb[c];
        }

        // ---- epilogue: acc[i][d] = acc*alpha + sum_jj v1[jj][d]*U[(i,jj)][d] ----
        float contrib[4] = {0.f, 0.f, 0.f, 0.f};
        #pragma unroll
        for (int r = 0; r < 4; r++) {
            int jj = ((ty & 1) << 2) + r;
            #pragma unroll
            for (int c = 0; c < 4; c++)
                contrib[c] += V1s[(jj << 6) + (tx << 2) + c] * u[r][c];
        }
        #pragma unroll
        for (int c = 0; c < 4; c++)
            contrib[c] += __shfl_xor_sync(0xffffffffu, contrib[c], 16);
        if (lane < 16) {
            float al = sAl[warp];
            #pragma unroll
            for (int c = 0; c < 4; c++) {
                int ai = (warp << 6) + (tx << 2) + c;
                accS[ai] = accS[ai] * al + contrib[c];
            }
        }
        __syncthreads();
    }

    // ---- finalize: out[i][d] = acc/Z ----
    if (lane < 16) {
        float invZ = 1.0f / sZ[warp];
        int d4 = tx << 2;
        float4 o;
        o.x = accS[(warp << 6) + d4 + 0] * invZ;
        o.y = accS[(warp << 6) + d4 + 1] * invZ;
        o.z = accS[(warp << 6) + d4 + 2] * invZ;
        o.w = accS[(warp << 6) + d4 + 3] * invZ;
        *(float4*)&outp[(size_t)(b * T_ + i0 + warp) * C_ + h * D_ + d4] = o;
    }
}

// ---------------------------------------------------------------------------
extern "C" void kernel_launch(void* const* d_in, const int* in_sizes, int n_in,
                              void* d_out, int out_size)
{
    const float* x     = (const float*)d_in[0];
    const float* W_in  = (const float*)d_in[1];
    const float* b_in  = (const float*)d_in[2];
    const float* W_out = (const float*)d_in[3];
    const float* b_out = (const float*)d_in[4];
    float* y = (float*)d_out;

    float *proj, *attn;
    cudaGetSymbolAddress((void**)&proj, g_proj);
    cudaGetSymbolAddress((void**)&attn, g_attn);

    const size_t SMEM = (size_t)SMEM_FLOATS * sizeof(float);  // 175,200 B
    cudaFuncSetAttribute(attn_kernel,
                         cudaFuncAttributeMaxDynamicSharedMemorySize, (int)SMEM);

    // 1) proj = x @ W_in + b_in : (384,512)@(512,2560)
    dim3 g1(PROJC / 64, (B_ * T_) / 64);
    gemm_bias_kernel<<<g1, 256>>>(x, W_in, b_in, proj, B_ * T_, PROJC, C_);

    // 2) fused two-simplicial attention
    dim3 ga(T_ / 8, H_, B_);
    attn_kernel<<<ga, 256, SMEM>>>(proj, attn);

    // 3) y = attn @ W_out + b_out : (384,512)@(512,512)
    dim3 g2(C_ / 64, (B_ * T_) / 64);
    gemm_bias_kernel<<<g2, 256>>>(attn, W_out, b_out, y, B_ * T_, C_, C_);
}

// round 3
// speedup vs baseline: 2.5476x; 2.5476x over previous
#include <cuda_runtime.h>
#include <cstdint>

#define B_ 2
#define T_ 192
#define C_ 512
#define H_ 8
#define D_ 64
#define PROJC (5 * C_)  // 2560

// scratch (device globals; no allocation allowed)
__device__ float g_proj[B_ * T_ * PROJC];
__device__ float g_attn[B_ * T_ * C_];

// ---------------------------------------------------------------------------
// Generic tiled GEMM + bias (fp32 SIMT) — used for proj and output GEMMs.
// ---------------------------------------------------------------------------
__global__ __launch_bounds__(256) void gemm_bias_kernel(
    const float* __restrict__ A, const float* __restrict__ Bm,
    const float* __restrict__ bias, float* __restrict__ C,
    int M, int N, int K)
{
    __shared__ float AsT[16][65];
    __shared__ float Bs[16][64];

    const int t  = threadIdx.x;
    const int tx = t & 15;
    const int ty = t >> 4;
    const int row0 = blockIdx.y * 64;
    const int col0 = blockIdx.x * 64;

    float acc[4][4] = {};

    for (int kt = 0; kt < K; kt += 16) {
        {
            int r  = t >> 2;
            int c4 = (t & 3) << 2;
            float4 av = *(const float4*)&A[(size_t)(row0 + r) * K + kt + c4];
            AsT[c4 + 0][r] = av.x; AsT[c4 + 1][r] = av.y;
            AsT[c4 + 2][r] = av.z; AsT[c4 + 3][r] = av.w;
        }
        {
            int r  = t >> 4;
            int c4 = (t & 15) << 2;
            *(float4*)&Bs[r][c4] = *(const float4*)&Bm[(size_t)(kt + r) * N + col0 + c4];
        }
        __syncthreads();

        #pragma unroll
        for (int kk = 0; kk < 16; kk++) {
            float a[4];
            #pragma unroll
            for (int r = 0; r < 4; r++) a[r] = AsT[kk][(ty << 2) + r];
            float4 bv = *(float4*)&Bs[kk][tx << 2];
            float bb[4] = {bv.x, bv.y, bv.z, bv.w};
            #pragma unroll
            for (int r = 0; r < 4; r++)
                #pragma unroll
                for (int c = 0; c < 4; c++)
                    acc[r][c] += a[r] * bb[c];
        }
        __syncthreads();
    }

    #pragma unroll
    for (int r = 0; r < 4; r++) {
        float4 o;
        int col = col0 + (tx << 2);
        o.x = acc[r][0] + bias[col + 0];
        o.y = acc[r][1] + bias[col + 1];
        o.z = acc[r][2] + bias[col + 2];
        o.w = acc[r][3] + bias[col + 3];
        *(float4*)&C[(size_t)(row0 + (ty << 2) + r) * N + col] = o;
    }
}

// ---------------------------------------------------------------------------
// tf32 mma helpers
// ---------------------------------------------------------------------------
__device__ __forceinline__ unsigned f2tf(float f) {
    unsigned r;
    asm("cvt.rna.tf32.f32 %0, %1;" : "=r"(r) : "f"(f));
    return r;
}

__device__ __forceinline__ void mma8(float* c, const unsigned* a,
                                     unsigned b0, unsigned b1) {
    asm volatile(
        "mma.sync.aligned.m16n8k8.row.col.f32.tf32.tf32.f32 "
        "{%0,%1,%2,%3},{%4,%5,%6,%7},{%8,%9},{%0,%1,%2,%3};\n"
        : "+f"(c[0]), "+f"(c[1]), "+f"(c[2]), "+f"(c[3])
        : "r"(a[0]), "r"(a[1]), "r"(a[2]), "r"(a[3]), "r"(b0), "r"(b1));
}

// permutation within each 8-wide group: stored pos s = 2*(r&3) | (r>>2)
// so that stored cols {k0+2t, k0+2t+1} = original cols {k0+t, k0+t+4}
__device__ __forceinline__ int perm_s(int d) {
    int r = d & 7;
    return (d & ~7) | (((r & 3) << 1) | (r >> 2));
}

// ---------------------------------------------------------------------------
// Fused two-simplicial attention with tf32 tensor cores.
// One block per (b, h, i-tile of 8). 256 threads / 8 warps.
// ---------------------------------------------------------------------------

// shared layout (float offsets; all even)
#define OFF_QP   0        // 512  Qp[8][64]  (permuted, scaled)
#define OFF_K1P  512      // 512  K1p[8][64] (permuted)
#define OFF_V1   1024     // 512  V1s[8][64] (natural)
#define OFF_ACC  1536     // 512  accS[8][64]
#define OFF_SM   2048     // 8
#define OFF_SZ   2056     // 8
#define OFF_SAL  2064     // 8
#define OFF_RM   2072     // 32   redM[4][8]
#define OFF_RZ   2104     // 32   redZ[4][8]
#define OFF_PP   2144     // 4608  Pp[64][72]  (P permuted; reused as U0)
#define OFF_UP   6752     // 4608  Upart[64][72] (U1)
#define OFF_K2   11360    // 13824 K2n[192][72] (k-major, d permuted)
#define OFF_V2T  25184    // 12800 V2T[64][200] (d-major, k permuted)
#define OFF_EM   37984    // 12800 Em[64][200]  (m-major, k permuted)
#define SMEM_FLOATS 50784

__global__ __launch_bounds__(256, 1) void attn_kernel(
    const float* __restrict__ proj, float* __restrict__ outp)
{
    extern __shared__ float sm[];
    float* Qp   = sm + OFF_QP;
    float* K1p  = sm + OFF_K1P;
    float* V1s  = sm + OFF_V1;
    float* accS = sm + OFF_ACC;
    float* sM   = sm + OFF_SM;
    float* sZ   = sm + OFF_SZ;
    float* sAl  = sm + OFF_SAL;
    float* redM = sm + OFF_RM;
    float* redZ = sm + OFF_RZ;
    float* Pp   = sm + OFF_PP;
    float* Up   = sm + OFF_UP;
    float* K2n  = sm + OFF_K2;
    float* V2T  = sm + OFF_V2T;
    float* Em   = sm + OFF_EM;

    const int t    = threadIdx.x;
    const int lane = t & 31;
    const int w    = t >> 5;
    const int grp  = lane >> 2;
    const int tid4 = lane & 3;
    const int b    = blockIdx.z;
    const int h    = blockIdx.y;
    const int i0   = blockIdx.x * 8;

    const float* base = proj + (size_t)b * T_ * PROJC + h * D_;
    // proj row layout: q:0  k1:C_  v1:2C_  k2:3C_  v2:4C_

    // ---- init: Qp (scaled, permuted), acc, stats, K2n, V2T ----
    for (int idx = t; idx < 512; idx += 256) {
        int r = idx >> 6, d = idx & 63;
        Qp[(r << 6) + perm_s(d)] = base[(size_t)(i0 + r) * PROJC + d] * 0.125f;
        accS[idx] = 0.f;
    }
    if (t < 8) { sM[t] = -3.0e38f; sZ[t] = 0.f; sAl[t] = 0.f; }
    for (int idx = t; idx < T_ * D_; idx += 256) {
        int k = idx >> 6, d = idx & 63;
        K2n[k * 72 + perm_s(d)] =
            __uint_as_float(f2tf(base[(size_t)k * PROJC + 3 * C_ + d]));
        V2T[d * 200 + perm_s(k)] =
            __uint_as_float(f2tf(base[(size_t)k * PROJC + 4 * C_ + d]));
    }
    __syncthreads();

    // warp roles
    const int wm  = w & 1;          // GEMM1: rows 32*wm .. +32
    const int wn  = w >> 1;         // GEMM1: cols 48*wn .. +48
    const int wm2 = w & 1;          // GEMM2
    const int wn2 = (w >> 1) & 1;
    const int wk  = (w >> 2) & 1;

    // Em store positions for C-fragment cols r=2*tid4, 2*tid4+1
    const int r0c = 2 * tid4, r1c = 2 * tid4 + 1;
    const int es0 = (((r0c & 3) << 1) | (r0c >> 2));
    const int es1 = (((r1c & 3) << 1) | (r1c >> 2));

    for (int jt = 0; jt < T_; jt += 8) {
        // ---- (1) load K1 (permuted) / V1 (natural) for this j-tile ----
        {
            int tt = t & 127;
            int jj = tt >> 4, d4 = (tt & 15) << 2;
            const float* src = base + (size_t)(jt + jj) * PROJC +
                               (t < 128 ? C_ : 2 * C_) + d4;
            float4 v = *(const float4*)src;
            if (t < 128) {
                int b8 = d4 & ~7;
                int o0 = (d4 & 4) ? 1 : 0;
                K1p[(jj << 6) + b8 + o0 + 0] = v.x;
                K1p[(jj << 6) + b8 + o0 + 2] = v.y;
                K1p[(jj << 6) + b8 + o0 + 4] = v.z;
                K1p[(jj << 6) + b8 + o0 + 6] = v.w;
            } else {
                *(float4*)&V1s[(jj << 6) + d4] = v;
            }
        }
        __syncthreads();

        // ---- (2) P[m][s] = Qp[i][s]*K1p[jj][s], tf32-rounded ----
        #pragma unroll
        for (int l = 0; l < 16; l++) {
            int idx = t + (l << 8);
            int m = idx >> 6, s = idx & 63;
            int i = m >> 3, jj = m & 7;
            Pp[m * 72 + s] =
                __uint_as_float(f2tf(Qp[(i << 6) + s] * K1p[(jj << 6) + s]));
        }
        __syncthreads();

        // ---- (3) GEMM1: S[64x192] = P[64x64] @ K2^T, tf32 MMA ----
        float c1[2][6][4];
        #pragma unroll
        for (int a = 0; a < 2; a++)
            #pragma unroll
            for (int n = 0; n < 6; n++)
                #pragma unroll
                for (int q = 0; q < 4; q++) c1[a][n][q] = 0.f;

        {
            const int arow = (wm << 5) + grp;
            #pragma unroll
            for (int k = 0; k < 8; k++) {
                const int kc = (k << 3) + (tid4 << 1);
                unsigned a0[4], a1[4];
                uint2 x;
                x = *(const uint2*)&Pp[(arow +  0) * 72 + kc]; a0[0]=x.x; a0[2]=x.y;
                x = *(const uint2*)&Pp[(arow +  8) * 72 + kc]; a0[1]=x.x; a0[3]=x.y;
                x = *(const uint2*)&Pp[(arow + 16) * 72 + kc]; a1[0]=x.x; a1[2]=x.y;
                x = *(const uint2*)&Pp[(arow + 24) * 72 + kc]; a1[1]=x.x; a1[3]=x.y;
                #pragma unroll
                for (int n = 0; n < 6; n++) {
                    uint2 bv = *(const uint2*)&K2n[(wn * 48 + (n << 3) + grp) * 72 + kc];
                    mma8(c1[0][n], a0, bv.x, bv.y);
                    mma8(c1[1][n], a1, bv.x, bv.y);
                }
            }
        }

        // ---- row-max per i-slot; slots: s=2a+half, i = 4*wm + s ----
        float mx[4] = {-3.0e38f, -3.0e38f, -3.0e38f, -3.0e38f};
        #pragma unroll
        for (int a = 0; a < 2; a++)
            #pragma unroll
            for (int n = 0; n < 6; n++) {
                mx[2*a+0] = fmaxf(mx[2*a+0], fmaxf(c1[a][n][0], c1[a][n][1]));
                mx[2*a+1] = fmaxf(mx[2*a+1], fmaxf(c1[a][n][2], c1[a][n][3]));
            }
        #pragma unroll
        for (int s = 0; s < 4; s++)
            #pragma unroll
            for (int off = 16; off > 0; off >>= 1)
                mx[s] = fmaxf(mx[s], __shfl_xor_sync(0xffffffffu, mx[s], off));
        if (lane == 0) {
            #pragma unroll
            for (int s = 0; s < 4; s++)
                redM[(wn << 3) + (wm << 2) + s] = mx[s];
        }
        __syncthreads();

        // ---- Mnew per slot ----
        float Mnew[4];
        #pragma unroll
        for (int s = 0; s < 4; s++) {
            int i = (wm << 2) + s;
            float m0 = sM[i];
            #pragma unroll
            for (int q = 0; q < 4; q++) m0 = fmaxf(m0, redM[(q << 3) + i]);
            Mnew[s] = m0;
        }

        // ---- exp, store E (permuted, tf32), partial Z ----
        float zs[4] = {0.f, 0.f, 0.f, 0.f};
        #pragma unroll
        for (int a = 0; a < 2; a++) {
            const int rr = (wm << 5) + (a << 4) + grp;
            #pragma unroll
            for (int n = 0; n < 6; n++) {
                const int n0 = wn * 48 + (n << 3);
                float e0 = __expf(c1[a][n][0] - Mnew[2*a+0]);
                float e1 = __expf(c1[a][n][1] - Mnew[2*a+0]);
                float e2 = __expf(c1[a][n][2] - Mnew[2*a+1]);
                float e3 = __expf(c1[a][n][3] - Mnew[2*a+1]);
                zs[2*a+0] += e0 + e1;
                zs[2*a+1] += e2 + e3;
                Em[rr * 200 + n0 + es0]       = __uint_as_float(f2tf(e0));
                Em[rr * 200 + n0 + es1]       = __uint_as_float(f2tf(e1));
                Em[(rr + 8) * 200 + n0 + es0] = __uint_as_float(f2tf(e2));
                Em[(rr + 8) * 200 + n0 + es1] = __uint_as_float(f2tf(e3));
            }
        }
        #pragma unroll
        for (int s = 0; s < 4; s++)
            #pragma unroll
            for (int off = 16; off > 0; off >>= 1)
                zs[s] += __shfl_xor_sync(0xffffffffu, zs[s], off);
        if (lane == 0) {
            #pragma unroll
            for (int s = 0; s < 4; s++)
                redZ[(wn << 3) + (wm << 2) + s] = zs[s];
        }
        __syncthreads();

        // ---- stats update (one thread per i) ----
        if (t < 8) {
            float Mo = sM[t];
            float Mn = Mo;
            #pragma unroll
            for (int q = 0; q < 4; q++) Mn = fmaxf(Mn, redM[(q << 3) + t]);
            float alpha = __expf(Mo - Mn);
            float zsum = 0.f;
            #pragma unroll
            for (int q = 0; q < 4; q++) zsum += redZ[(q << 3) + t];
            sZ[t]  = sZ[t] * alpha + zsum;
            sM[t]  = Mn;
            sAl[t] = alpha;
        }

        // ---- (4) GEMM2: U[64x64] = E[64x192] @ V2, tf32 MMA, K split ----
        float u2[2][4][4];
        #pragma unroll
        for (int a = 0; a < 2; a++)
            #pragma unroll
            for (int n = 0; n < 4; n++)
                #pragma unroll
                for (int q = 0; q < 4; q++) u2[a][n][q] = 0.f;

        {
            const int arow = (wm2 << 5) + grp;
            #pragma unroll
            for (int ks = 0; ks < 12; ks++) {
                const int kc = wk * 96 + (ks << 3) + (tid4 << 1);
                unsigned a0[4], a1[4];
                uint2 x;
                x = *(const uint2*)&Em[(arow +  0) * 200 + kc]; a0[0]=x.x; a0[2]=x.y;
                x = *(const uint2*)&Em[(arow +  8) * 200 + kc]; a0[1]=x.x; a0[3]=x.y;
                x = *(const uint2*)&Em[(arow + 16) * 200 + kc]; a1[0]=x.x; a1[2]=x.y;
                x = *(const uint2*)&Em[(arow + 24) * 200 + kc]; a1[1]=x.x; a1[3]=x.y;
                #pragma unroll
                for (int n = 0; n < 4; n++) {
                    uint2 bv = *(const uint2*)&V2T[((wn2 << 5) + (n << 3) + grp) * 200 + kc];
                    mma8(u2[0][n], a0, bv.x, bv.y);
                    mma8(u2[1][n], a1, bv.x, bv.y);
                }
            }
            float* dst = wk ? Up : Pp;
            #pragma unroll
            for (int a = 0; a < 2; a++)
                #pragma unroll
                for (int n = 0; n < 4; n++) {
                    int rr = (wm2 << 5) + (a << 4) + grp;
                    int cc = (wn2 << 5) + (n << 3) + (tid4 << 1);
                    float2 lo = make_float2(u2[a][n][0], u2[a][n][1]);
                    float2 hi = make_float2(u2[a][n][2], u2[a][n][3]);
                    *(float2*)&dst[rr * 72 + cc]       = lo;
                    *(float2*)&dst[(rr + 8) * 72 + cc] = hi;
                }
        }
        __syncthreads();

        // ---- (5) epilogue: acc[i][d] = acc*alpha + sum_jj V1[jj][d]*U[m][d] ----
        {
            const int i  = t >> 5;
            const int dc = lane << 1;
            float2 acc = *(float2*)&accS[(i << 6) + dc];
            float alpha = sAl[i];
            acc.x *= alpha; acc.y *= alpha;
            #pragma unroll
            for (int jj = 0; jj < 8; jj++) {
                int m = (i << 3) + jj;
                float2 u0 = *(float2*)&Pp[m * 72 + dc];
                float2 u1 = *(float2*)&Up[m * 72 + dc];
                float2 v1 = *(float2*)&V1s[(jj << 6) + dc];
                acc.x += v1.x * (u0.x + u1.x);
                acc.y += v1.y * (u0.y + u1.y);
            }
            *(float2*)&accS[(i << 6) + dc] = acc;
        }
        __syncthreads();
    }

    // ---- finalize ----
    {
        const int i  = t >> 5;
        const int dc = lane << 1;
        float invZ = 1.0f / sZ[i];
        float2 acc = *(float2*)&accS[(i << 6) + dc];
        acc.x *= invZ; acc.y *= invZ;
        *(float2*)&outp[(size_t)(b * T_ + i0 + i) * C_ + h * D_ + dc] = acc;
    }
}

// ---------------------------------------------------------------------------
extern "C" void kernel_launch(void* const* d_in, const int* in_sizes, int n_in,
                              void* d_out, int out_size)
{
    const float* x     = (const float*)d_in[0];
    const float* W_in  = (const float*)d_in[1];
    const float* b_in  = (const float*)d_in[2];
    const float* W_out = (const float*)d_in[3];
    const float* b_out = (const float*)d_in[4];
    float* y = (float*)d_out;

    float *proj, *attn;
    cudaGetSymbolAddress((void**)&proj, g_proj);
    cudaGetSymbolAddress((void**)&attn, g_attn);

    const size_t SMEM = (size_t)SMEM_FLOATS * sizeof(float);  // 203,136 B
    cudaFuncSetAttribute(attn_kernel,
                         cudaFuncAttributeMaxDynamicSharedMemorySize, (int)SMEM);

    // 1) proj = x @ W_in + b_in
    dim3 g1(PROJC / 64, (B_ * T_) / 64);
    gemm_bias_kernel<<<g1, 256>>>(x, W_in, b_in, proj, B_ * T_, PROJC, C_);

    // 2) fused two-simplicial attention (tf32 tensor cores)
    dim3 ga(T_ / 8, H_, B_);
    attn_kernel<<<ga, 256, SMEM>>>(proj, attn);

    // 3) y = attn @ W_out + b_out
    dim3 g2(C_ / 64, (B_ * T_) / 64);
    gemm_bias_kernel<<<g2, 256>>>(attn, W_out, b_out, y, B_ * T_, C_, C_);
}

// round 4
// speedup vs baseline: 3.7749x; 1.4818x over previous
#include <cuda_runtime.h>
#include <cuda_fp16.h>
#include <cstdint>

#define B_ 2
#define T_ 192
#define C_ 512
#define H_ 8
#define D_ 64
#define PROJC (5 * C_)  // 2560

__device__ float g_proj[B_ * T_ * PROJC];
__device__ float g_attn[B_ * T_ * C_];

// ---------------------------------------------------------------------------
// SIMT fp32 GEMM + bias, 32x32 tile, 128 threads (high block count)
// ---------------------------------------------------------------------------
__global__ __launch_bounds__(128) void gemm32_kernel(
    const float* __restrict__ A, const float* __restrict__ Bm,
    const float* __restrict__ bias, float* __restrict__ C,
    int M, int N, int K)
{
    __shared__ float AsT[16][34];
    __shared__ float Bs[16][32];

    const int t  = threadIdx.x;
    const int tx = t & 7;
    const int ty = t >> 3;
    const int row0 = blockIdx.y * 32;
    const int col0 = blockIdx.x * 32;

    float acc[2][4] = {};

    for (int kt = 0; kt < K; kt += 16) {
        {
            int r  = t >> 2;
            int c4 = (t & 3) << 2;
            float4 av = *(const float4*)&A[(size_t)(row0 + r) * K + kt + c4];
            AsT[c4 + 0][r] = av.x; AsT[c4 + 1][r] = av.y;
            AsT[c4 + 2][r] = av.z; AsT[c4 + 3][r] = av.w;
        }
        {
            int r  = t >> 3;
            int c4 = (t & 7) << 2;
            *(float4*)&Bs[r][c4] = *(const float4*)&Bm[(size_t)(kt + r) * N + col0 + c4];
        }
        __syncthreads();

        #pragma unroll
        for (int kk = 0; kk < 16; kk++) {
            float2 av = *(float2*)&AsT[kk][ty << 1];
            float4 bv = *(float4*)&Bs[kk][tx << 2];
            acc[0][0] += av.x * bv.x; acc[0][1] += av.x * bv.y;
            acc[0][2] += av.x * bv.z; acc[0][3] += av.x * bv.w;
            acc[1][0] += av.y * bv.x; acc[1][1] += av.y * bv.y;
            acc[1][2] += av.y * bv.z; acc[1][3] += av.y * bv.w;
        }
        __syncthreads();
    }

    #pragma unroll
    for (int r = 0; r < 2; r++) {
        int col = col0 + (tx << 2);
        float4 o;
        o.x = acc[r][0] + bias[col + 0];
        o.y = acc[r][1] + bias[col + 1];
        o.z = acc[r][2] + bias[col + 2];
        o.w = acc[r][3] + bias[col + 3];
        *(float4*)&C[(size_t)(row0 + (ty << 1) + r) * N + col] = o;
    }
}

// ---------------------------------------------------------------------------
// fp16 mma helpers
// ---------------------------------------------------------------------------
__device__ __forceinline__ void mma16816(float* c, const unsigned* a,
                                         unsigned b0, unsigned b1) {
    asm volatile(
        "mma.sync.aligned.m16n8k16.row.col.f32.f16.f16.f32 "
        "{%0,%1,%2,%3},{%4,%5,%6,%7},{%8,%9},{%0,%1,%2,%3};\n"
        : "+f"(c[0]), "+f"(c[1]), "+f"(c[2]), "+f"(c[3])
        : "r"(a[0]), "r"(a[1]), "r"(a[2]), "r"(a[3]), "r"(b0), "r"(b1));
}

__device__ __forceinline__ unsigned packh2(float lo, float hi) {
    __half2 h = __floats2half2_rn(lo, hi);
    return *(unsigned*)&h;
}

// ---------------------------------------------------------------------------
// Fused two-simplicial attention, fp16 tensor cores, register-resident E.
// One block per (b,h,i-tile of 8). 8 warps. Per j-tile of 8:
//   Ph[m][d]   (half2 pairs)   = q_i * k1_jj
//   S = Ph @ K2h^T  (m16n8k16, warp (wm,wn): rows 32wm+, cols 48wn+)
//   online softmax in regs -> E packed directly into GEMM2 A-fragments
//   U_partial = E_slice @ V2h  (per-warp partial over its 48 k's)
//   epilogue: acc = acc*alpha + sum_jj V1 * (sum of 4 partials)
// ---------------------------------------------------------------------------

#define OFF_Q    0        // 512   Qs[8][64] fp32 (prescaled)
#define OFF_K1   512      // 512   K1s[8][64] fp32
#define OFF_V1   1024     // 512   V1s[8][64] fp32
#define OFF_ACC  1536     // 512   accS[8][64] fp32
#define OFF_SM   2048     // 8
#define OFF_SZ   2056     // 8
#define OFF_SAL  2064     // 8
#define OFF_RM   2072     // 32    redM[4][8]
#define OFF_RZ   2104     // 32    redZ[4][8]
#define OFF_PH   2144     // 2304  Ph[64][36]  half2 words
#define OFF_K2H  4448     // 6912  K2h[192][36] half2 words (d-pairs)
#define OFF_V2H  11360    // 6912  V2h[96][72]  half2 words (k-pairs x d)
#define OFF_UP   18272    // 18432 Upar[4][64][72] fp32
#define SMEM_FLOATS 36704  // 146,816 B

__global__ __launch_bounds__(256, 1) void attn_kernel(
    const float* __restrict__ proj, float* __restrict__ outp)
{
    extern __shared__ float sm[];
    float* Qs   = sm + OFF_Q;
    float* K1s  = sm + OFF_K1;
    float* V1s  = sm + OFF_V1;
    float* accS = sm + OFF_ACC;
    float* sM   = sm + OFF_SM;
    float* sZ   = sm + OFF_SZ;
    float* sAl  = sm + OFF_SAL;
    float* redM = sm + OFF_RM;
    float* redZ = sm + OFF_RZ;
    unsigned* Ph  = (unsigned*)(sm + OFF_PH);
    unsigned* K2h = (unsigned*)(sm + OFF_K2H);
    unsigned* V2h = (unsigned*)(sm + OFF_V2H);
    float* Upar = sm + OFF_UP;

    const int t    = threadIdx.x;
    const int lane = t & 31;
    const int w    = t >> 5;
    const int grp  = lane >> 2;
    const int tid4 = lane & 3;
    const int b    = blockIdx.z;
    const int h    = blockIdx.y;
    const int i0   = blockIdx.x * 8;

    const float* base = proj + (size_t)b * T_ * PROJC + h * D_;
    // proj row: q:0  k1:C_  v1:2C_  k2:3C_  v2:4C_

    // ---- init ----
    for (int idx = t; idx < 512; idx += 256) {
        int r = idx >> 6, d = idx & 63;
        Qs[idx]   = base[(size_t)(i0 + r) * PROJC + d] * 0.125f;
        accS[idx] = 0.f;
    }
    if (t < 8) { sM[t] = -3.0e38f; sZ[t] = 0.f; sAl[t] = 0.f; }
    // K2h[k][p] = half2(K2[k][2p], K2[k][2p+1])
    for (int idx = t; idx < 192 * 32; idx += 256) {
        int k = idx >> 5, p = idx & 31;
        float2 v = *(const float2*)&base[(size_t)k * PROJC + 3 * C_ + 2 * p];
        K2h[k * 36 + p] = packh2(v.x, v.y);
    }
    // V2h[pr][d] = half2(V2[2pr][d], V2[2pr+1][d])
    for (int idx = t; idx < 96 * 64; idx += 256) {
        int pr = idx >> 6, d = idx & 63;
        float lo = base[(size_t)(2 * pr)     * PROJC + 4 * C_ + d];
        float hi = base[(size_t)(2 * pr + 1) * PROJC + 4 * C_ + d];
        V2h[pr * 72 + d] = packh2(lo, hi);
    }
    __syncthreads();

    const int wm = w & 1;
    const int wn = w >> 1;

    for (int jt = 0; jt < T_; jt += 8) {
        // ---- (1) K1/V1 rows for this j-tile ----
        {
            int tt = t & 127;
            int jj = tt >> 4, d4 = (tt & 15) << 2;
            const float* src = base + (size_t)(jt + jj) * PROJC +
                               (t < 128 ? C_ : 2 * C_) + d4;
            float* dst = (t < 128 ? K1s : V1s) + (jj << 6) + d4;
            *(float4*)dst = *(const float4*)src;
        }
        __syncthreads();

        // ---- (2) P build: Ph[m][d-pair] half2 ----
        #pragma unroll
        for (int l = 0; l < 4; l++) {
            int idx = t + (l << 8);          // 0..1023
            int m = idx >> 4, q4 = idx & 15; // d = 4*q4
            int i = m >> 3, jj = m & 7;
            float4 qv = *(float4*)&Qs[(i << 6) + (q4 << 2)];
            float4 kv = *(float4*)&K1s[(jj << 6) + (q4 << 2)];
            uint2 pk;
            pk.x = packh2(qv.x * kv.x, qv.y * kv.y);
            pk.y = packh2(qv.z * kv.z, qv.w * kv.w);
            *(uint2*)&Ph[m * 36 + (q4 << 1)] = pk;
        }
        __syncthreads();

        // ---- (3) GEMM1: S[64x192] ----
        float c1[2][6][4] = {};
        {
            const int raBase = (wm << 5) + grp;
            #pragma unroll
            for (int kk = 0; kk < 4; kk++) {
                unsigned A[2][4];
                #pragma unroll
                for (int a = 0; a < 2; a++) {
                    int ra = raBase + (a << 4);
                    A[a][0] = Ph[ra * 36 + (kk << 3) + tid4];
                    A[a][1] = Ph[(ra + 8) * 36 + (kk << 3) + tid4];
                    A[a][2] = Ph[ra * 36 + (kk << 3) + 4 + tid4];
                    A[a][3] = Ph[(ra + 8) * 36 + (kk << 3) + 4 + tid4];
                }
                #pragma unroll
                for (int n = 0; n < 6; n++) {
                    int row = wn * 48 + (n << 3) + grp;
                    unsigned b0 = K2h[row * 36 + (kk << 3) + tid4];
                    unsigned b1 = K2h[row * 36 + (kk << 3) + 4 + tid4];
                    mma16816(c1[0][n], A[0], b0, b1);
                    mma16816(c1[1][n], A[1], b0, b1);
                }
            }
        }

        // ---- row-max ----
        float mx[4] = {-3.0e38f, -3.0e38f, -3.0e38f, -3.0e38f};
        #pragma unroll
        for (int a = 0; a < 2; a++)
            #pragma unroll
            for (int n = 0; n < 6; n++) {
                mx[2*a+0] = fmaxf(mx[2*a+0], fmaxf(c1[a][n][0], c1[a][n][1]));
                mx[2*a+1] = fmaxf(mx[2*a+1], fmaxf(c1[a][n][2], c1[a][n][3]));
            }
        #pragma unroll
        for (int s = 0; s < 4; s++)
            #pragma unroll
            for (int off = 16; off > 0; off >>= 1)
                mx[s] = fmaxf(mx[s], __shfl_xor_sync(0xffffffffu, mx[s], off));
        if (lane == 0) {
            #pragma unroll
            for (int s = 0; s < 4; s++)
                redM[(wn << 3) + (wm << 2) + s] = mx[s];
        }
        __syncthreads();

        float Mnew[4];
        #pragma unroll
        for (int s = 0; s < 4; s++) {
            int i = (wm << 2) + s;
            float m0 = sM[i];
            #pragma unroll
            for (int q = 0; q < 4; q++) m0 = fmaxf(m0, redM[(q << 3) + i]);
            Mnew[s] = m0;
        }

        // ---- exp -> E packed directly as GEMM2 A-fragments ----
        unsigned ea[2][3][4];
        float zs[4] = {0.f, 0.f, 0.f, 0.f};
        #pragma unroll
        for (int a = 0; a < 2; a++)
            #pragma unroll
            for (int n = 0; n < 6; n++) {
                float e0 = __expf(c1[a][n][0] - Mnew[2*a+0]);
                float e1 = __expf(c1[a][n][1] - Mnew[2*a+0]);
                float e2 = __expf(c1[a][n][2] - Mnew[2*a+1]);
                float e3 = __expf(c1[a][n][3] - Mnew[2*a+1]);
                zs[2*a+0] += e0 + e1;
                zs[2*a+1] += e2 + e3;
                unsigned p0 = packh2(e0, e1);
                unsigned p1 = packh2(e2, e3);
                if (n & 1) { ea[a][n >> 1][2] = p0; ea[a][n >> 1][3] = p1; }
                else       { ea[a][n >> 1][0] = p0; ea[a][n >> 1][1] = p1; }
            }
        #pragma unroll
        for (int s = 0; s < 4; s++)
            #pragma unroll
            for (int off = 16; off > 0; off >>= 1)
                zs[s] += __shfl_xor_sync(0xffffffffu, zs[s], off);
        if (lane == 0) {
            #pragma unroll
            for (int s = 0; s < 4; s++)
                redZ[(wn << 3) + (wm << 2) + s] = zs[s];
        }
        __syncthreads();

        if (t < 8) {
            float Mo = sM[t];
            float Mn = Mo;
            #pragma unroll
            for (int q = 0; q < 4; q++) Mn = fmaxf(Mn, redM[(q << 3) + t]);
            float alpha = __expf(Mo - Mn);
            float zsum = 0.f;
            #pragma unroll
            for (int q = 0; q < 4; q++) zsum += redZ[(q << 3) + t];
            sZ[t]  = sZ[t] * alpha + zsum;
            sM[t]  = Mn;
            sAl[t] = alpha;
        }

        // ---- (4) GEMM2: partial U over this warp's 48 k's ----
        float u[2][8][4] = {};
        #pragma unroll
        for (int kk2 = 0; kk2 < 3; kk2++) {
            int rb = 24 * wn + (kk2 << 3);
            #pragma unroll
            for (int n = 0; n < 8; n++) {
                unsigned b0 = V2h[(rb + tid4) * 72 + (n << 3) + grp];
                unsigned b1 = V2h[(rb + 4 + tid4) * 72 + (n << 3) + grp];
                mma16816(u[0][n], ea[0][kk2], b0, b1);
                mma16816(u[1][n], ea[1][kk2], b0, b1);
            }
        }
        {
            float* Us = Upar + wn * 64 * 72;
            #pragma unroll
            for (int a = 0; a < 2; a++)
                #pragma unroll
                for (int n = 0; n < 8; n++) {
                    int r  = (wm << 5) + (a << 4) + grp;
                    int cc = (n << 3) + (tid4 << 1);
                    *(float2*)&Us[r * 72 + cc] =
                        make_float2(u[a][n][0], u[a][n][1]);
                    *(float2*)&Us[(r + 8) * 72 + cc] =
                        make_float2(u[a][n][2], u[a][n][3]);
                }
        }
        __syncthreads();

        // ---- (5) epilogue ----
        {
            const int i  = t >> 5;
            const int dc = lane << 1;
            float2 acc = *(float2*)&accS[(i << 6) + dc];
            float al = sAl[i];
            acc.x *= al; acc.y *= al;
            #pragma unroll
            for (int jj = 0; jj < 8; jj++) {
                int m = (i << 3) + jj;
                float sx = 0.f, sy = 0.f;
                #pragma unroll
                for (int q = 0; q < 4; q++) {
                    float2 uq = *(float2*)&Upar[(q * 64 + m) * 72 + dc];
                    sx += uq.x; sy += uq.y;
                }
                float2 v1 = *(float2*)&V1s[(jj << 6) + dc];
                acc.x += v1.x * sx;
                acc.y += v1.y * sy;
            }
            *(float2*)&accS[(i << 6) + dc] = acc;
        }
        __syncthreads();
    }

    // ---- finalize ----
    {
        const int i  = t >> 5;
        const int dc = lane << 1;
        float invZ = 1.0f / sZ[i];
        float2 acc = *(float2*)&accS[(i << 6) + dc];
        acc.x *= invZ; acc.y *= invZ;
        *(float2*)&outp[(size_t)(b * T_ + i0 + i) * C_ + h * D_ + dc] = acc;
    }
}

// ---------------------------------------------------------------------------
extern "C" void kernel_launch(void* const* d_in, const int* in_sizes, int n_in,
                              void* d_out, int out_size)
{
    const float* x     = (const float*)d_in[0];
    const float* W_in  = (const float*)d_in[1];
    const float* b_in  = (const float*)d_in[2];
    const float* W_out = (const float*)d_in[3];
    const float* b_out = (const float*)d_in[4];
    float* y = (float*)d_out;

    float *proj, *attn;
    cudaGetSymbolAddress((void**)&proj, g_proj);
    cudaGetSymbolAddress((void**)&attn, g_attn);

    const size_t SMEM = (size_t)SMEM_FLOATS * sizeof(float);  // 146,816 B
    cudaFuncSetAttribute(attn_kernel,
                         cudaFuncAttributeMaxDynamicSharedMemorySize, (int)SMEM);

    // 1) proj = x @ W_in + b_in : (384,512)@(512,2560), 960 blocks
    dim3 g1(PROJC / 32, (B_ * T_) / 32);
    gemm32_kernel<<<g1, 128>>>(x, W_in, b_in, proj, B_ * T_, PROJC, C_);

    // 2) fused attention (fp16 tensor cores)
    dim3 ga(T_ / 8, H_, B_);
    attn_kernel<<<ga, 256, SMEM>>>(proj, attn);

    // 3) y = attn @ W_out + b_out : (384,512)@(512,512), 192 blocks
    dim3 g2(C_ / 32, (B_ * T_) / 32);
    gemm32_kernel<<<g2, 128>>>(attn, W_out, b_out, y, B_ * T_, C_, C_);
}

// round 5
// speedup vs baseline: 5.7397x; 1.5205x over previous
#include <cuda_runtime.h>
#include <cuda_fp16.h>
#include <cstdint>

#define B_ 2
#define T_ 192
#define C_ 512
#define H_ 8
#define D_ 64
#define PROJC (5 * C_)  // 2560

__device__ float g_proj[B_ * T_ * PROJC];
__device__ float g_attn[B_ * T_ * C_];

// ---------------------------------------------------------------------------
// helpers
// ---------------------------------------------------------------------------
__device__ __forceinline__ unsigned f2tf(float f) {
    unsigned r;
    asm("cvt.rna.tf32.f32 %0, %1;" : "=r"(r) : "f"(f));
    return r;
}
__device__ __forceinline__ void mma8(float* c, const unsigned* a,
                                     unsigned b0, unsigned b1) {
    asm volatile(
        "mma.sync.aligned.m16n8k8.row.col.f32.tf32.tf32.f32 "
        "{%0,%1,%2,%3},{%4,%5,%6,%7},{%8,%9},{%0,%1,%2,%3};\n"
        : "+f"(c[0]), "+f"(c[1]), "+f"(c[2]), "+f"(c[3])
        : "r"(a[0]), "r"(a[1]), "r"(a[2]), "r"(a[3]), "r"(b0), "r"(b1));
}
__device__ __forceinline__ void mma16816(float* c, const unsigned* a,
                                         unsigned b0, unsigned b1) {
    asm volatile(
        "mma.sync.aligned.m16n8k16.row.col.f32.f16.f16.f32 "
        "{%0,%1,%2,%3},{%4,%5,%6,%7},{%8,%9},{%0,%1,%2,%3};\n"
        : "+f"(c[0]), "+f"(c[1]), "+f"(c[2]), "+f"(c[3])
        : "r"(a[0]), "r"(a[1]), "r"(a[2]), "r"(a[3]), "r"(b0), "r"(b1));
}
__device__ __forceinline__ unsigned packh2(float lo, float hi) {
    __half2 h = __floats2half2_rn(lo, hi);
    return *(unsigned*)&h;
}

// ---------------------------------------------------------------------------
// tf32 tensor-core GEMM + bias: C[M,N] = A[M,K] @ Bm[K,N] + bias[N]
// 64x64 tile, 128 threads (4 warps, 2x2), K-step 16, reg-prefetch pipeline.
// M,N divisible by 64; K divisible by 16.
// ---------------------------------------------------------------------------
__global__ __launch_bounds__(128) void gemm_tc_kernel(
    const float* __restrict__ A, const float* __restrict__ Bm,
    const float* __restrict__ bias, float* __restrict__ C,
    int M, int N, int K)
{
    __shared__ float As[64][20];   // tf32 bits, row-major [m][k]
    __shared__ float Bs[16][72];   // tf32 bits, [k][n]

    const int t    = threadIdx.x;
    const int lane = t & 31;
    const int w    = t >> 5;
    const int grp  = lane >> 2;
    const int tid4 = lane & 3;
    const int wm   = w & 1;
    const int wn   = w >> 1;
    const int row0 = blockIdx.y * 64;
    const int col0 = blockIdx.x * 64;

    // loader indices
    const int ar = t >> 2;             // 0..31 (A rows; +32 second)
    const int ac = (t & 3) << 2;       // A col4
    const int br = t >> 4;             // 0..7 (B rows; +8 second)
    const int bc = (t & 15) << 2;      // B col4

    float4 pa0 = *(const float4*)&A[(size_t)(row0 + ar) * K + ac];
    float4 pa1 = *(const float4*)&A[(size_t)(row0 + ar + 32) * K + ac];
    float4 pb0 = *(const float4*)&Bm[(size_t)br * N + col0 + bc];
    float4 pb1 = *(const float4*)&Bm[(size_t)(br + 8) * N + col0 + bc];

    float c[2][4][4] = {};

    for (int kt = 0; kt < K; kt += 16) {
        // store staged tiles (converted to tf32)
        As[ar][ac + 0]      = __uint_as_float(f2tf(pa0.x));
        As[ar][ac + 1]      = __uint_as_float(f2tf(pa0.y));
        As[ar][ac + 2]      = __uint_as_float(f2tf(pa0.z));
        As[ar][ac + 3]      = __uint_as_float(f2tf(pa0.w));
        As[ar + 32][ac + 0] = __uint_as_float(f2tf(pa1.x));
        As[ar + 32][ac + 1] = __uint_as_float(f2tf(pa1.y));
        As[ar + 32][ac + 2] = __uint_as_float(f2tf(pa1.z));
        As[ar + 32][ac + 3] = __uint_as_float(f2tf(pa1.w));
        {
            float4 v0, v1;
            v0.x = __uint_as_float(f2tf(pb0.x)); v0.y = __uint_as_float(f2tf(pb0.y));
            v0.z = __uint_as_float(f2tf(pb0.z)); v0.w = __uint_as_float(f2tf(pb0.w));
            v1.x = __uint_as_float(f2tf(pb1.x)); v1.y = __uint_as_float(f2tf(pb1.y));
            v1.z = __uint_as_float(f2tf(pb1.z)); v1.w = __uint_as_float(f2tf(pb1.w));
            *(float4*)&Bs[br][bc]     = v0;
            *(float4*)&Bs[br + 8][bc] = v1;
        }
        __syncthreads();

        if (kt + 16 < K) {
            pa0 = *(const float4*)&A[(size_t)(row0 + ar) * K + kt + 16 + ac];
            pa1 = *(const float4*)&A[(size_t)(row0 + ar + 32) * K + kt + 16 + ac];
            pb0 = *(const float4*)&Bm[(size_t)(kt + 16 + br) * N + col0 + bc];
            pb1 = *(const float4*)&Bm[(size_t)(kt + 16 + br + 8) * N + col0 + bc];
        }

        #pragma unroll
        for (int kk = 0; kk < 2; kk++) {
            const int k8 = kk << 3;
            unsigned a[2][4];
            #pragma unroll
            for (int mt = 0; mt < 2; mt++) {
                int r = (wm << 5) + (mt << 4) + grp;
                a[mt][0] = __float_as_uint(As[r][k8 + tid4]);
                a[mt][1] = __float_as_uint(As[r + 8][k8 + tid4]);
                a[mt][2] = __float_as_uint(As[r][k8 + tid4 + 4]);
                a[mt][3] = __float_as_uint(As[r + 8][k8 + tid4 + 4]);
            }
            #pragma unroll
            for (int n = 0; n < 4; n++) {
                int cc = (wn << 5) + (n << 3) + grp;
                unsigned b0 = __float_as_uint(Bs[k8 + tid4][cc]);
                unsigned b1 = __float_as_uint(Bs[k8 + tid4 + 4][cc]);
                mma8(c[0][n], a[0], b0, b1);
                mma8(c[1][n], a[1], b0, b1);
            }
        }
        __syncthreads();
    }

    // epilogue
    #pragma unroll
    for (int mt = 0; mt < 2; mt++) {
        #pragma unroll
        for (int n = 0; n < 4; n++) {
            int row = row0 + (wm << 5) + (mt << 4) + grp;
            int col = col0 + (wn << 5) + (n << 3) + (tid4 << 1);
            float2 bv = *(const float2*)&bias[col];
            float2 o0 = make_float2(c[mt][n][0] + bv.x, c[mt][n][1] + bv.y);
            float2 o1 = make_float2(c[mt][n][2] + bv.x, c[mt][n][3] + bv.y);
            *(float2*)&C[(size_t)row * N + col]       = o0;
            *(float2*)&C[(size_t)(row + 8) * N + col] = o1;
        }
    }
}

// ---------------------------------------------------------------------------
// Fused two-simplicial attention, fp16 mma, register E, fp16 U-partials,
// 2 blocks/SM, software-pipelined K1/V1 loads.
// ---------------------------------------------------------------------------

#define OFF_Q    0        // 512   Qs[8][64] fp32 (prescaled)
#define OFF_K1   512      // 512   K1s[8][64] fp32
#define OFF_V1   1024     // 512   V1s[8][64] fp32
#define OFF_ACC  1536     // 512   accS[8][64] fp32
#define OFF_SM   2048     // 8
#define OFF_SZ   2056     // 8
#define OFF_SAL  2064     // 8
#define OFF_RM   2072     // 32    redM[4][8]
#define OFF_RZ   2104     // 32    redZ[4][8]
#define OFF_PH   2144     // 2304  Ph[64][36]  half2 words
#define OFF_K2H  4448     // 6912  K2h[192][36] half2 words (d-pairs)
#define OFF_V2H  11360    // 6912  V2h[96][72]  half2 words (k-pairs x d)
#define OFF_UH   18272    // 9216  Uh[4][64][36] half2 words
#define SMEM_FLOATS 27488  // 109,952 B

__global__ __launch_bounds__(256, 2) void attn_kernel(
    const float* __restrict__ proj, float* __restrict__ outp)
{
    extern __shared__ float sm[];
    float* Qs   = sm + OFF_Q;
    float* K1s  = sm + OFF_K1;
    float* V1s  = sm + OFF_V1;
    float* accS = sm + OFF_ACC;
    float* sM   = sm + OFF_SM;
    float* sZ   = sm + OFF_SZ;
    float* sAl  = sm + OFF_SAL;
    float* redM = sm + OFF_RM;
    float* redZ = sm + OFF_RZ;
    unsigned* Ph  = (unsigned*)(sm + OFF_PH);
    unsigned* K2h = (unsigned*)(sm + OFF_K2H);
    unsigned* V2h = (unsigned*)(sm + OFF_V2H);
    unsigned* Uh  = (unsigned*)(sm + OFF_UH);

    const int t    = threadIdx.x;
    const int lane = t & 31;
    const int w    = t >> 5;
    const int grp  = lane >> 2;
    const int tid4 = lane & 3;
    const int b    = blockIdx.z;
    const int h    = blockIdx.y;
    const int i0   = blockIdx.x * 8;

    const float* base = proj + (size_t)b * T_ * PROJC + h * D_;
    // proj row: q:0  k1:C_  v1:2C_  k2:3C_  v2:4C_

    // K1/V1 pipeline loader role
    const int ttp  = t & 127;
    const int jjp  = ttp >> 4;
    const int d4p  = (ttp & 15) << 2;
    const float* pfbase = base + (size_t)jjp * PROJC +
                          (t < 128 ? C_ : 2 * C_) + d4p;
    float* pfdst = (t < 128 ? K1s : V1s) + (jjp << 6) + d4p;

    // ---- init ----
    float4 preg = *(const float4*)pfbase;   // tile 0
    for (int idx = t; idx < 512; idx += 256) {
        int r = idx >> 6, d = idx & 63;
        Qs[idx]   = base[(size_t)(i0 + r) * PROJC + d] * 0.125f;
        accS[idx] = 0.f;
    }
    if (t < 8) { sM[t] = -3.0e38f; sZ[t] = 0.f; sAl[t] = 0.f; }
    for (int idx = t; idx < 192 * 32; idx += 256) {
        int k = idx >> 5, p = idx & 31;
        float2 v = *(const float2*)&base[(size_t)k * PROJC + 3 * C_ + 2 * p];
        K2h[k * 36 + p] = packh2(v.x, v.y);
    }
    for (int idx = t; idx < 96 * 64; idx += 256) {
        int pr = idx >> 6, d = idx & 63;
        float lo = base[(size_t)(2 * pr)     * PROJC + 4 * C_ + d];
        float hi = base[(size_t)(2 * pr + 1) * PROJC + 4 * C_ + d];
        V2h[pr * 72 + d] = packh2(lo, hi);
    }
    __syncthreads();

    const int wm = w & 1;
    const int wn = w >> 1;

    for (int jt = 0; jt < T_; jt += 8) {
        // ---- (0) commit staged K1/V1 for THIS tile ----
        *(float4*)pfdst = preg;
        __syncthreads();
        // prefetch NEXT tile (lands during this iteration)
        if (jt + 8 < T_)
            preg = *(const float4*)(pfbase + (size_t)(jt + 8) * PROJC);

        // ---- (1) P build: Ph[m][d-pair] half2 ----
        #pragma unroll
        for (int l = 0; l < 4; l++) {
            int idx = t + (l << 8);
            int m = idx >> 4, q4 = idx & 15;
            int i = m >> 3, jj = m & 7;
            float4 qv = *(float4*)&Qs[(i << 6) + (q4 << 2)];
            float4 kv = *(float4*)&K1s[(jj << 6) + (q4 << 2)];
            uint2 pk;
            pk.x = packh2(qv.x * kv.x, qv.y * kv.y);
            pk.y = packh2(qv.z * kv.z, qv.w * kv.w);
            *(uint2*)&Ph[m * 36 + (q4 << 1)] = pk;
        }
        __syncthreads();

        // ---- (2) GEMM1: S[64x192] ----
        float c1[2][6][4] = {};
        {
            const int raBase = (wm << 5) + grp;
            #pragma unroll
            for (int kk = 0; kk < 4; kk++) {
                unsigned A[2][4];
                #pragma unroll
                for (int a = 0; a < 2; a++) {
                    int ra = raBase + (a << 4);
                    A[a][0] = Ph[ra * 36 + (kk << 3) + tid4];
                    A[a][1] = Ph[(ra + 8) * 36 + (kk << 3) + tid4];
                    A[a][2] = Ph[ra * 36 + (kk << 3) + 4 + tid4];
                    A[a][3] = Ph[(ra + 8) * 36 + (kk << 3) + 4 + tid4];
                }
                #pragma unroll
                for (int n = 0; n < 6; n++) {
                    int row = wn * 48 + (n << 3) + grp;
                    unsigned b0 = K2h[row * 36 + (kk << 3) + tid4];
                    unsigned b1 = K2h[row * 36 + (kk << 3) + 4 + tid4];
                    mma16816(c1[0][n], A[0], b0, b1);
                    mma16816(c1[1][n], A[1], b0, b1);
                }
            }
        }

        // ---- (3) online softmax ----
        float mx[4] = {-3.0e38f, -3.0e38f, -3.0e38f, -3.0e38f};
        #pragma unroll
        for (int a = 0; a < 2; a++)
            #pragma unroll
            for (int n = 0; n < 6; n++) {
                mx[2*a+0] = fmaxf(mx[2*a+0], fmaxf(c1[a][n][0], c1[a][n][1]));
                mx[2*a+1] = fmaxf(mx[2*a+1], fmaxf(c1[a][n][2], c1[a][n][3]));
            }
        #pragma unroll
        for (int s = 0; s < 4; s++)
            #pragma unroll
            for (int off = 16; off > 0; off >>= 1)
                mx[s] = fmaxf(mx[s], __shfl_xor_sync(0xffffffffu, mx[s], off));
        if (lane == 0) {
            #pragma unroll
            for (int s = 0; s < 4; s++)
                redM[(wn << 3) + (wm << 2) + s] = mx[s];
        }
        __syncthreads();

        float Mnew[4];
        #pragma unroll
        for (int s = 0; s < 4; s++) {
            int i = (wm << 2) + s;
            float m0 = sM[i];
            #pragma unroll
            for (int q = 0; q < 4; q++) m0 = fmaxf(m0, redM[(q << 3) + i]);
            Mnew[s] = m0;
        }

        unsigned ea[2][3][4];
        float zs[4] = {0.f, 0.f, 0.f, 0.f};
        #pragma unroll
        for (int a = 0; a < 2; a++)
            #pragma unroll
            for (int n = 0; n < 6; n++) {
                float e0 = __expf(c1[a][n][0] - Mnew[2*a+0]);
                float e1 = __expf(c1[a][n][1] - Mnew[2*a+0]);
                float e2 = __expf(c1[a][n][2] - Mnew[2*a+1]);
                float e3 = __expf(c1[a][n][3] - Mnew[2*a+1]);
                zs[2*a+0] += e0 + e1;
                zs[2*a+1] += e2 + e3;
                unsigned p0 = packh2(e0, e1);
                unsigned p1 = packh2(e2, e3);
                if (n & 1) { ea[a][n >> 1][2] = p0; ea[a][n >> 1][3] = p1; }
                else       { ea[a][n >> 1][0] = p0; ea[a][n >> 1][1] = p1; }
            }
        #pragma unroll
        for (int s = 0; s < 4; s++)
            #pragma unroll
            for (int off = 16; off > 0; off >>= 1)
                zs[s] += __shfl_xor_sync(0xffffffffu, zs[s], off);
        if (lane == 0) {
            #pragma unroll
            for (int s = 0; s < 4; s++)
                redZ[(wn << 3) + (wm << 2) + s] = zs[s];
        }
        __syncthreads();

        if (t < 8) {
            float Mo = sM[t];
            float Mn = Mo;
            #pragma unroll
            for (int q = 0; q < 4; q++) Mn = fmaxf(Mn, redM[(q << 3) + t]);
            float alpha = __expf(Mo - Mn);
            float zsum = 0.f;
            #pragma unroll
            for (int q = 0; q < 4; q++) zsum += redZ[(q << 3) + t];
            sZ[t]  = sZ[t] * alpha + zsum;
            sM[t]  = Mn;
            sAl[t] = alpha;
        }

        // ---- (4) GEMM2 partial U (fp16 out), two n-halves to cap regs ----
        #pragma unroll
        for (int nh = 0; nh < 2; nh++) {
            float u[2][4][4] = {};
            #pragma unroll
            for (int kk2 = 0; kk2 < 3; kk2++) {
                int rb = 24 * wn + (kk2 << 3);
                #pragma unroll
                for (int n = 0; n < 4; n++) {
                    int nn = (nh << 2) + n;
                    unsigned b0 = V2h[(rb + tid4) * 72 + (nn << 3) + grp];
                    unsigned b1 = V2h[(rb + 4 + tid4) * 72 + (nn << 3) + grp];
                    mma16816(u[0][n], ea[0][kk2], b0, b1);
                    mma16816(u[1][n], ea[1][kk2], b0, b1);
                }
            }
            unsigned* Uq = Uh + wn * 2304;
            #pragma unroll
            for (int a = 0; a < 2; a++)
                #pragma unroll
                for (int n = 0; n < 4; n++) {
                    int nn = (nh << 2) + n;
                    int r  = (wm << 5) + (a << 4) + grp;
                    int cw = (nn << 2) + tid4;
                    Uq[r * 36 + cw]       = packh2(u[a][n][0], u[a][n][1]);
                    Uq[(r + 8) * 36 + cw] = packh2(u[a][n][2], u[a][n][3]);
                }
        }
        __syncthreads();

        // ---- (5) epilogue ----
        {
            const int i  = t >> 5;
            float2 acc = *(float2*)&accS[(i << 6) + (lane << 1)];
            float al = sAl[i];
            acc.x *= al; acc.y *= al;
            #pragma unroll
            for (int jj = 0; jj < 8; jj++) {
                int m = (i << 3) + jj;
                float sx = 0.f, sy = 0.f;
                #pragma unroll
                for (int q = 0; q < 4; q++) {
                    unsigned uw = Uh[q * 2304 + m * 36 + lane];
                    float2 f = __half22float2(*(__half2*)&uw);
                    sx += f.x; sy += f.y;
                }
                float2 v1 = *(float2*)&V1s[(jj << 6) + (lane << 1)];
                acc.x += v1.x * sx;
                acc.y += v1.y * sy;
            }
            *(float2*)&accS[(i << 6) + (lane << 1)] = acc;
        }
        __syncthreads();
    }

    // ---- finalize ----
    {
        const int i  = t >> 5;
        float invZ = 1.0f / sZ[i];
        float2 acc = *(float2*)&accS[(i << 6) + (lane << 1)];
        acc.x *= invZ; acc.y *= invZ;
        *(float2*)&outp[(size_t)(b * T_ + i0 + i) * C_ + h * D_ + (lane << 1)] = acc;
    }
}

// ---------------------------------------------------------------------------
extern "C" void kernel_launch(void* const* d_in, const int* in_sizes, int n_in,
                              void* d_out, int out_size)
{
    const float* x     = (const float*)d_in[0];
    const float* W_in  = (const float*)d_in[1];
    const float* b_in  = (const float*)d_in[2];
    const float* W_out = (const float*)d_in[3];
    const float* b_out = (const float*)d_in[4];
    float* y = (float*)d_out;

    float *proj, *attn;
    cudaGetSymbolAddress((void**)&proj, g_proj);
    cudaGetSymbolAddress((void**)&attn, g_attn);

    const size_t SMEM = (size_t)SMEM_FLOATS * sizeof(float);  // 109,952 B
    cudaFuncSetAttribute(attn_kernel,
                         cudaFuncAttributeMaxDynamicSharedMemorySize, (int)SMEM);

    // 1) proj = x @ W_in + b_in : (384,512)@(512,2560)
    dim3 g1(PROJC / 64, (B_ * T_) / 64);
    gemm_tc_kernel<<<g1, 128>>>(x, W_in, b_in, proj, B_ * T_, PROJC, C_);

    // 2) fused attention
    dim3 ga(T_ / 8, H_, B_);
    attn_kernel<<<ga, 256, SMEM>>>(proj, attn);

    // 3) y = attn @ W_out + b_out : (384,512)@(512,512)
    dim3 g2(C_ / 64, (B_ * T_) / 64);
    gemm_tc_kernel<<<g2, 128>>>(attn, W_out, b_out, y, B_ * T_, C_, C_);
}